// round 2
// baseline (speedup 1.0000x reference)
#include <cuda_runtime.h>
#include <cuda_bf16.h>
#include <math.h>

// ---------------- problem constants ----------------
#define BB   256
#define LL   512
#define CC   32
#define NB   4
#define SEG  64
#define FREQ 8
#define STEP 4
#define DD   512
#define HH   1024
#define FIN  2048   // SEG*CC
#define FF   257    // L/2+1

// ---------------- scratch layout (floats) ----------------
// Aliasing: D1 reuses the XIT region (dead after xit_to_xi),
//           Dec reuses the Xi region (dead after enc1 GEMM).
static constexpr long OFF_MEAN  = 0;
static constexpr long OFF_STD   = OFF_MEAN  + 8192;
static constexpr long OFF_XNC   = OFF_STD   + 8192;
static constexpr long OFF_KKER  = OFF_XNC   + 8192L*512;
static constexpr long OFF_KC    = OFF_KKER  + 4L*512;
static constexpr long OFF_XIT   = OFF_KC    + 4L*512*512;      // 16.8M floats
static constexpr long OFF_XI    = OFF_XIT   + 4L*512*8192;     // 16.8M floats
static constexpr long OFF_E1    = OFF_XI    + 4L*2048*2048;
static constexpr long OFF_ENC   = OFF_E1    + 4L*2048*1024;
static constexpr long OFF_Y     = OFF_ENC   + 4L*2048*512;
static constexpr long OFF_HA    = OFF_Y     + 4L*2048*512;
static constexpr long OFF_HB    = OFF_HA    + 4L*256*512;
static constexpr long OFF_PREDS = OFF_HB    + 4L*256*512;
static constexpr long SCRATCH_TOTAL = OFF_PREDS + 4L*256*4*512;
// aliases (regions are large enough: D1 needs 4M floats <= 16.8M; Dec needs 8.4M <= 16.8M)
static constexpr long OFF_D1    = OFF_XIT;
static constexpr long OFF_DEC   = OFF_XI;

__device__ __align__(16) float g_scratch[SCRATCH_TOTAL];

// ---------------- instance-norm stats + transposed normalized input ----------------
// xnc[(b*32+c)][l] = (x[b][l][c]-mean[b][c]) / std[b][c]
__global__ void stats_xnc_kernel(const float* __restrict__ x, float* __restrict__ xnc,
                                 float* __restrict__ meanO, float* __restrict__ stdO)
{
    int b   = blockIdx.x;
    int tid = threadIdx.x;         // 256
    int c   = tid & 31;
    int ty  = tid >> 5;            // 0..7
    const float* xb = x + (long)b * LL * CC;

    float s = 0.f, s2 = 0.f;
    for (int l = ty; l < LL; l += 8) {
        float v = xb[l * CC + c];
        s += v; s2 += v * v;
    }
    __shared__ float sm[8][32], sm2[8][32];
    sm[ty][c] = s; sm2[ty][c] = s2;
    __syncthreads();
    __shared__ float smean[32], sinv[32];
    if (ty == 0) {
        float S = 0.f, S2 = 0.f;
        #pragma unroll
        for (int i = 0; i < 8; i++) { S += sm[i][c]; S2 += sm2[i][c]; }
        float mu  = S * (1.f / LL);
        float var = S2 * (1.f / LL) - mu * mu;
        float sd  = sqrtf(var + 1e-5f);
        smean[c] = mu; sinv[c] = 1.f / sd;
        meanO[b * 32 + c] = mu;
        stdO [b * 32 + c] = sd;
    }
    __syncthreads();

    __shared__ float tile[32][33];
    for (int l0 = 0; l0 < LL; l0 += 32) {
        #pragma unroll
        for (int i = 0; i < 4; i++) {
            int l = l0 + ty + i * 8;
            tile[ty + i * 8][c] = (xb[l * CC + c] - smean[c]) * sinv[c];
        }
        __syncthreads();
        #pragma unroll
        for (int i = 0; i < 4; i++) {
            int cc = ty + i * 8;   // channel
            int ll = c;            // l within tile
            xnc[((long)b * 32 + cc) * LL + l0 + ll] = tile[ll][cc];
        }
        __syncthreads();
    }
}

// ---------------- circular-convolution kernel from mask ----------------
// k[nb][d] = (1/512)(m0 + (-1)^d m256 + 2 * sum_{f=1..255} m_f cos(2*pi*f*d/512))
__global__ void kker_kernel(const float* __restrict__ mw, float* __restrict__ kker)
{
    int nb = blockIdx.x;
    int d  = threadIdx.x;          // 512
    __shared__ float m[FF];
    for (int f = threadIdx.x; f < FF; f += 512)
        m[f] = 1.f / (1.f + expf(-mw[nb * FF + f]));
    __syncthreads();
    float acc = m[0] + m[256] * ((d & 1) ? -1.f : 1.f);
    for (int f = 1; f < 256; f++) {
        int k = (f * d) & 511;
        acc += 2.f * m[f] * cospif((float)k * (1.f / 256.f));
    }
    kker[nb * 512 + d] = acc * (1.f / 512.f);
}

// Kc[nb][l][lp] = kker[nb][(l-lp) mod 512]
__global__ void kc_kernel(const float* __restrict__ kker, float* __restrict__ Kc)
{
    int nb = blockIdx.y, l = blockIdx.x;
    __shared__ float kr[512];
    kr[threadIdx.x] = kker[nb * 512 + threadIdx.x];
    __syncthreads();
    int lp = threadIdx.x;
    Kc[((long)nb * 512 + l) * 512 + lp] = kr[(l - lp + 512) & 511];
}

// ---------------- generic tiled NT GEMM:  C = A(MxK) @ B(NxK)^T (+bias)(+D)(relu) ----------------
template<int BM, int BN, int BK, int TM, int TN, bool RELU>
__global__ void __launch_bounds__((BM/TM)*(BN/TN))
gemm_nt(const float* __restrict__ A, const float* __restrict__ Bw,
        const float* __restrict__ bias, const float* __restrict__ Dadd,
        float* __restrict__ C,
        int K, int lda, int ldb, int ldc, int ldd,
        long sA, long sB, long sBias, long sD, long sC)
{
    constexpr int TX = BN / TN, TY = BM / TM, THREADS = TX * TY;
    __shared__ __align__(16) float As[BK][BM + 4];
    __shared__ __align__(16) float Bs[BK][BN + 4];

    long z = blockIdx.z;
    A  += z * sA;
    Bw += z * sB;
    C  += z * sC;
    if (bias) bias += z * sBias;
    if (Dadd) Dadd += z * sD;

    const int bm = blockIdx.y * BM, bn = blockIdx.x * BN;
    const int tid = threadIdx.x;
    const int tx = tid % TX, ty = tid / TX;

    float acc[TM][TN];
    #pragma unroll
    for (int i = 0; i < TM; i++)
        #pragma unroll
        for (int j = 0; j < TN; j++) acc[i][j] = 0.f;

    const float* Aptr = A  + (long)bm * lda;
    const float* Bptr = Bw + (long)bn * ldb;

    for (int k0 = 0; k0 < K; k0 += BK) {
        #pragma unroll
        for (int li = tid; li < BM * (BK / 4); li += THREADS) {
            int row = li / (BK / 4), kq = li % (BK / 4);
            float4 v = *(const float4*)(Aptr + (long)row * lda + k0 + kq * 4);
            As[kq*4+0][row] = v.x; As[kq*4+1][row] = v.y;
            As[kq*4+2][row] = v.z; As[kq*4+3][row] = v.w;
        }
        #pragma unroll
        for (int li = tid; li < BN * (BK / 4); li += THREADS) {
            int row = li / (BK / 4), kq = li % (BK / 4);
            float4 v = *(const float4*)(Bptr + (long)row * ldb + k0 + kq * 4);
            Bs[kq*4+0][row] = v.x; Bs[kq*4+1][row] = v.y;
            Bs[kq*4+2][row] = v.z; Bs[kq*4+3][row] = v.w;
        }
        __syncthreads();
        #pragma unroll
        for (int kk = 0; kk < BK; kk++) {
            float a[TM], bv[TN];
            #pragma unroll
            for (int i = 0; i < TM; i += 4) {
                float4 t4 = *(const float4*)&As[kk][ty * TM + i];
                a[i] = t4.x; a[i+1] = t4.y; a[i+2] = t4.z; a[i+3] = t4.w;
            }
            #pragma unroll
            for (int j = 0; j < TN; j += 4) {
                float4 t4 = *(const float4*)&Bs[kk][tx * TN + j];
                bv[j] = t4.x; bv[j+1] = t4.y; bv[j+2] = t4.z; bv[j+3] = t4.w;
            }
            #pragma unroll
            for (int i = 0; i < TM; i++)
                #pragma unroll
                for (int j = 0; j < TN; j++)
                    acc[i][j] += a[i] * bv[j];
        }
        __syncthreads();
    }

    #pragma unroll
    for (int i = 0; i < TM; i++) {
        int m = bm + ty * TM + i;
        #pragma unroll
        for (int j = 0; j < TN; j++) {
            int n = bn + tx * TN + j;
            float v = acc[i][j];
            if (bias) v += bias[n];
            if (Dadd) v += Dadd[(long)m * ldd + n];
            if (RELU) v = fmaxf(v, 0.f);
            C[(long)m * ldc + n] = v;
        }
    }
}

// ---------------- XiT [nb][l][b*32+c] -> Xi [nb][(b*8+f)][seg*32+c] ----------------
__global__ void xit_to_xi(const float* __restrict__ XiT, float* __restrict__ Xi)
{
    int id = blockIdx.x;                    // nb*2048 + b*8 + f
    int nb = id >> 11;
    int bf = id & 2047;
    int b = bf >> 3, f = bf & 7;
    const float* src = XiT + ((long)nb * 512 + f * 64) * 8192 + b * 32;
    float* dst = Xi + (long)id * 2048;
    for (int i = threadIdx.x; i < 2048; i += 256) {
        int seg = i >> 5, c = i & 31;
        dst[i] = src[(long)seg * 8192 + c];
    }
}

// ---------------- LayerNorm over last dim 512 ----------------
__global__ void ln_kernel(float* __restrict__ preds, const float* __restrict__ g,
                          const float* __restrict__ bb)
{
    long row = blockIdx.x;                  // nb*1024 + b*4 + s
    int nb = (int)(row >> 10);
    float* p = preds + row * 512;
    int t = threadIdx.x;                    // 256
    float v0 = p[t], v1 = p[t + 256];
    float s = v0 + v1, s2 = v0 * v0 + v1 * v1;
    #pragma unroll
    for (int o = 16; o; o >>= 1) {
        s  += __shfl_xor_sync(0xFFFFFFFFu, s,  o);
        s2 += __shfl_xor_sync(0xFFFFFFFFu, s2, o);
    }
    __shared__ float ws[8], ws2[8];
    if ((t & 31) == 0) { ws[t >> 5] = s; ws2[t >> 5] = s2; }
    __syncthreads();
    float S = 0.f, S2 = 0.f;
    #pragma unroll
    for (int i = 0; i < 8; i++) { S += ws[i]; S2 += ws2[i]; }
    float mu  = S * (1.f / 512.f);
    float inv = rsqrtf(S2 * (1.f / 512.f) - mu * mu + 1e-5f);
    p[t]       = (v0 - mu) * inv * g[nb * 512 + t]       + bb[nb * 512 + t];
    p[t + 256] = (v1 - mu) * inv * g[nb * 512 + t + 256] + bb[nb * 512 + t + 256];
}

// ---------------- sum over blocks + de-normalize ----------------
__global__ void combine_kernel(const float* __restrict__ Dec, const float* __restrict__ stdv,
                               const float* __restrict__ meanv, float* __restrict__ out)
{
    long o = (long)blockIdx.x * 256 + threadIdx.x;   // b*8192 + (s*64+p)*32 + c
    int b = (int)(o >> 13);
    int r = (int)(o & 8191);
    int t = r >> 5, c = r & 31;
    int s = t >> 6, p = t & 63;
    long idx = ((long)(b * 4 + s)) * 2048 + p * 32 + c;
    const long NBS = 1024L * 2048;
    float acc = Dec[idx] + Dec[idx + NBS] + Dec[idx + 2 * NBS] + Dec[idx + 3 * NBS];
    out[o] = acc * stdv[b * 32 + c] + meanv[b * 32 + c];
}

// ---------------- host orchestration ----------------
extern "C" void kernel_launch(void* const* d_in, const int* in_sizes, int n_in,
                              void* d_out, int out_size)
{
    const float* x_enc  = (const float*)d_in[0];
    const float* mask_w = (const float*)d_in[4];
    const float* enc_w1 = (const float*)d_in[5];
    const float* enc_b1 = (const float*)d_in[6];
    const float* enc_w2 = (const float*)d_in[7];
    const float* enc_b2 = (const float*)d_in[8];
    const float* wxh    = (const float*)d_in[9];
    const float* whh    = (const float*)d_in[10];
    const float* ln_g   = (const float*)d_in[11];
    const float* ln_b   = (const float*)d_in[12];
    const float* dec_w1 = (const float*)d_in[13];
    const float* dec_b1 = (const float*)d_in[14];
    const float* dec_w2 = (const float*)d_in[15];
    const float* dec_b2 = (const float*)d_in[16];

    float* sc = nullptr;
    cudaGetSymbolAddress((void**)&sc, g_scratch);
    float* g_mean  = sc + OFF_MEAN;
    float* g_std   = sc + OFF_STD;
    float* g_xnc   = sc + OFF_XNC;
    float* g_kker  = sc + OFF_KKER;
    float* g_kc    = sc + OFF_KC;
    float* g_xit   = sc + OFF_XIT;
    float* g_xi    = sc + OFF_XI;
    float* g_e1    = sc + OFF_E1;
    float* g_enc   = sc + OFF_ENC;
    float* g_y     = sc + OFF_Y;
    float* g_ha    = sc + OFF_HA;
    float* g_hb    = sc + OFF_HB;
    float* g_preds = sc + OFF_PREDS;
    float* g_d1    = sc + OFF_D1;
    float* g_dec   = sc + OFF_DEC;

    // 1) instance norm stats + normalized transposed input
    stats_xnc_kernel<<<256, 256>>>(x_enc, g_xnc, g_mean, g_std);

    // 2) circulant kernel + matrix
    kker_kernel<<<4, 512>>>(mask_w, g_kker);
    kc_kernel<<<dim3(512, 4), 512>>>(g_kker, g_kc);

    // 3) Fourier filter as GEMM: XiT[nb][l][bc] = Kc[nb] @ XnC^T
    gemm_nt<128, 64, 16, 8, 4, false><<<dim3(8192 / 64, 512 / 128, NB), 256>>>(
        g_kc, g_xnc, nullptr, nullptr, g_xit,
        512, 512, 512, 8192, 0,
        512L * 512, 0, 0, 0, 512L * 8192);

    // 4) relayout to encoder input
    xit_to_xi<<<8192, 256>>>(g_xit, g_xi);

    // 5) encoder MLP
    gemm_nt<128, 64, 16, 8, 4, true><<<dim3(1024 / 64, 2048 / 128, NB), 256>>>(
        g_xi, enc_w1, enc_b1, nullptr, g_e1,
        2048, 2048, 2048, 1024, 0,
        2048L * 2048, 1024L * 2048, 1024, 0, 2048L * 1024);
    gemm_nt<128, 64, 16, 8, 4, false><<<dim3(512 / 64, 2048 / 128, NB), 256>>>(
        g_e1, enc_w2, enc_b2, nullptr, g_enc,
        1024, 1024, 1024, 512, 0,
        2048L * 1024, 512L * 1024, 512, 0, 2048L * 512);

    // 6) Y = Enc @ Wxh^T  (all timesteps at once)
    gemm_nt<128, 64, 16, 8, 4, false><<<dim3(512 / 64, 2048 / 128, NB), 256>>>(
        g_enc, wxh, nullptr, nullptr, g_y,
        512, 512, 512, 512, 0,
        2048L * 512, 512L * 512, 0, 0, 2048L * 512);

    // 7) RNN recurrence: h_t = h_{t-1} @ Whh^T + Y_t   (h_0 = Y_0)
    float* hbuf[2] = { g_hb, g_ha };   // t odd -> g_ha
    for (int t = 1; t < 8; t++) {
        const float* Aop = (t == 1) ? g_y : hbuf[(t - 1) & 1];
        int  lda_t = (t == 1) ? 4096 : 512;
        long sA_t  = (t == 1) ? 2048L * 512 : 256L * 512;
        gemm_nt<32, 64, 16, 4, 4, false><<<dim3(512 / 64, 256 / 32, NB), 128>>>(
            Aop, whh, nullptr, g_y + t * 512, hbuf[t & 1],
            512, lda_t, 512, 512, 4096,
            sA_t, 512L * 512, 0, 2048L * 512, 256L * 512);
    }

    // 8) free-run predictions: preds_s = preds_{s-1} @ Whh^T  (preds_0 = h_7 in g_ha)
    for (int s = 1; s <= 4; s++) {
        const float* Aop = (s == 1) ? g_ha : (g_preds + (s - 2) * 512);
        int  lda_s = (s == 1) ? 512 : 2048;
        long sA_s  = (s == 1) ? 256L * 512 : 256L * 4 * 512;
        gemm_nt<32, 64, 16, 4, 4, false><<<dim3(512 / 64, 256 / 32, NB), 128>>>(
            Aop, whh, nullptr, nullptr, g_preds + (s - 1) * 512,
            512, lda_s, 512, 2048, 0,
            sA_s, 512L * 512, 0, 0, 256L * 4 * 512);
    }

    // 9) LayerNorm (in place)
    ln_kernel<<<4096, 256>>>(g_preds, ln_g, ln_b);

    // 10) decoder MLP
    gemm_nt<128, 64, 16, 8, 4, true><<<dim3(1024 / 64, 1024 / 128, NB), 256>>>(
        g_preds, dec_w1, dec_b1, nullptr, g_d1,
        512, 512, 512, 1024, 0,
        256L * 4 * 512, 1024L * 512, 1024, 0, 1024L * 1024);
    gemm_nt<128, 64, 16, 8, 4, false><<<dim3(2048 / 64, 1024 / 128, NB), 256>>>(
        g_d1, dec_w2, dec_b2, nullptr, g_dec,
        1024, 1024, 1024, 2048, 0,
        1024L * 1024, 2048L * 1024, 2048, 0, 1024L * 2048);

    // 11) sum blocks, de-normalize, reshape to [B, 256, 32]
    combine_kernel<<<8192, 256>>>(g_dec, g_std, g_mean, (float*)d_out);
}